// round 10
// baseline (speedup 1.0000x reference)
#include <cuda_runtime.h>
#include <math.h>

// CTC loss forward. Single-warp CTA, per-thread block-floating-point.
// B=64, T=1000, C=128 (blank=127), L=100, S=201.
// 32 threads/CTA; thread i owns pairs 4i..4i+3 (positions 8i..8i+7) as
// 4 float2 mantissa pairs + one shared int exponent E (true = mant*2^E).
// Per iteration (4 time steps): shfl neighbor's 4 pairs + exponent,
// rescale both sides to max exponent (exact 2^d bit-built), 4-layer
// packed-FMA pyramid (7+6+5+4 f32x2 updates), renormalize by exact 2^-e.
// NO barrier, NO shared memory, NO MUFU in the loop.

#define Bc 64
#define Tc 1000
#define Cc 128
#define Lc 100
#define NT 32

#define EPSV (1e-7f)
#define LN2F 0.6931471805599453f

__device__ __forceinline__ float lg2a(float x) {
    float y; asm("lg2.approx.f32 %0, %1;" : "=f"(y) : "f"(x)); return y;
}
__device__ __forceinline__ float2 add2(float2 a, float2 b) {
    float2 r;
    asm("{\n\t.reg .b64 A,B,D;\n\t"
        "mov.b64 A,{%2,%3};\n\tmov.b64 B,{%4,%5};\n\t"
        "add.rn.f32x2 D,A,B;\n\t"
        "mov.b64 {%0,%1},D;\n\t}"
        : "=f"(r.x), "=f"(r.y)
        : "f"(a.x), "f"(a.y), "f"(b.x), "f"(b.y));
    return r;
}
__device__ __forceinline__ float2 mul2(float2 a, float2 b) {
    float2 r;
    asm("{\n\t.reg .b64 A,B,D;\n\t"
        "mov.b64 A,{%2,%3};\n\tmov.b64 B,{%4,%5};\n\t"
        "mul.rn.f32x2 D,A,B;\n\t"
        "mov.b64 {%0,%1},D;\n\t}"
        : "=f"(r.x), "=f"(r.y)
        : "f"(a.x), "f"(a.y), "f"(b.x), "f"(b.y));
    return r;
}
__device__ __forceinline__ float2 fma2(float2 a, float2 b, float2 c) {
    float2 r;
    asm("{\n\t.reg .b64 A,B,C,D;\n\t"
        "mov.b64 A,{%2,%3};\n\tmov.b64 B,{%4,%5};\n\tmov.b64 C,{%6,%7};\n\t"
        "fma.rn.f32x2 D,A,B,C;\n\t"
        "mov.b64 {%0,%1},D;\n\t}"
        : "=f"(r.x), "=f"(r.y)
        : "f"(a.x), "f"(a.y), "f"(b.x), "f"(b.y), "f"(c.x), "f"(c.y));
    return r;
}
// 2^d for int d, clamped to 0 below representable range. Exact.
__device__ __forceinline__ float exp2i(int d) {
    int e = 127 + d; e = e < 0 ? 0 : e;
    return __int_as_float(e << 23);
}
// One CTC step for a pair: lo = (v2p + v2p-1)*pb; hi = (v2p+1 + v2p + sk*v2p-1)*po
__device__ __forceinline__ float2 upd(float2 Q, float2 Qm1, float skf, float2 P) {
    float2 S1 = make_float2(Qm1.y, Q.x);
    return mul2(fma2(make_float2(0.f, skf), Qm1, add2(Q, S1)), P);
}

__global__ __launch_bounds__(NT, 1)
void ctc_loss_kernel(const int* __restrict__ y_true,
                     const float* __restrict__ y_pred,
                     const int* __restrict__ input_len,
                     const int* __restrict__ label_len,
                     float* __restrict__ out)
{
    const int b = blockIdx.x;
    const int i = threadIdx.x;                 // 0..31
    const int* lab = y_true + b * Lc;

    // Static info for pairs 4i-3..4i+3 (clamped; garbage pairs harmless —
    // transitions only flow upward in s).
    int lofs[7]; float sk[7]; int lcls3 = 0;
    #pragma unroll
    for (int k = 0; k < 7; ++k) {
        int pj = 4 * i - 3 + k;
        int cj = pj < 0 ? 0 : (pj > Lc - 1 ? Lc - 1 : pj);
        int c  = lab[cj];
        int cp = lab[cj > 0 ? cj - 1 : 0];
        sk[k]   = (pj >= 1 && c != cp) ? 1.f : 0.f;
        lofs[k] = c * 4;
        if (k == 3) lcls3 = c;
    }

    int Tb = input_len[b]; if (Tb > Tc) Tb = Tc;
    const int smax = 2 * label_len[b];
    const char* base = (const char*)(y_pred + (size_t)b * Tc * Cc);

    // BFP state: 4 mantissa pairs + exponent.
    float2 A[4] = {{0.f,0.f},{0.f,0.f},{0.f,0.f},{0.f,0.f}};
    int E = 0;
    if (i == 0) {
        const float* r0 = (const float*)base;
        A[0] = make_float2(r0[Cc - 1] + EPSV, r0[lcls3] + EPSV);
    }

    // Prefetch probabilities for first iteration (rows 1..4; Tb >= 500).
    float pn1[7], pn2[6], pn3[5], pn4[4], pnb[4];
    {
        const char* rp = base + 512;
        #pragma unroll
        for (int k = 0; k < 7; ++k) pn1[k] = *(const float*)(rp +        lofs[k]);
        #pragma unroll
        for (int k = 0; k < 6; ++k) pn2[k] = *(const float*)(rp + 512  + lofs[k+1]);
        #pragma unroll
        for (int k = 0; k < 5; ++k) pn3[k] = *(const float*)(rp + 1024 + lofs[k+2]);
        #pragma unroll
        for (int k = 0; k < 4; ++k) pn4[k] = *(const float*)(rp + 1536 + lofs[k+3]);
        #pragma unroll
        for (int k = 0; k < 4; ++k) pnb[k] = *(const float*)(rp + 512*k + 508);
    }

    int t = 1;
    for (; t + 3 < Tb; t += 4) {
        // Pack current probabilities (+eps).
        float b0 = pnb[0]+EPSV, b1 = pnb[1]+EPSV, b2 = pnb[2]+EPSV, b3 = pnb[3]+EPSV;
        float2 P1[7], P2[6], P3[5], P4[4];
        #pragma unroll
        for (int k = 0; k < 7; ++k) P1[k] = make_float2(b0, pn1[k]+EPSV);
        #pragma unroll
        for (int k = 0; k < 6; ++k) P2[k] = make_float2(b1, pn2[k]+EPSV);
        #pragma unroll
        for (int k = 0; k < 5; ++k) P3[k] = make_float2(b2, pn3[k]+EPSV);
        #pragma unroll
        for (int k = 0; k < 4; ++k) P4[k] = make_float2(b3, pn4[k]+EPSV);

        // Neighbor exchange: 4 pairs + exponent via shfl (no barrier).
        float2 N[4]; int En;
        #pragma unroll
        for (int j = 0; j < 4; ++j) {
            N[j].x = __shfl_up_sync(0xffffffffu, A[j].x, 1);
            N[j].y = __shfl_up_sync(0xffffffffu, A[j].y, 1);
        }
        En = __shfl_up_sync(0xffffffffu, E, 1);
        if (i == 0) { N[0]=N[1]=N[2]=N[3]=make_float2(0.f,0.f); En = E; }

        // Prefetch next iteration's probabilities (clamped row base).
        {
            int rn = t + 4; if (rn > Tb - 4) rn = Tb - 4;
            const char* rp = base + (size_t)rn * 512;
            #pragma unroll
            for (int k = 0; k < 7; ++k) pn1[k] = *(const float*)(rp +        lofs[k]);
            #pragma unroll
            for (int k = 0; k < 6; ++k) pn2[k] = *(const float*)(rp + 512  + lofs[k+1]);
            #pragma unroll
            for (int k = 0; k < 5; ++k) pn3[k] = *(const float*)(rp + 1024 + lofs[k+2]);
            #pragma unroll
            for (int k = 0; k < 4; ++k) pn4[k] = *(const float*)(rp + 1536 + lofs[k+3]);
            #pragma unroll
            for (int k = 0; k < 4; ++k) pnb[k] = *(const float*)(rp + 512*k + 508);
        }

        // Rescale both sides to the common (max) exponent. Exact powers of 2.
        int Em = E > En ? E : En;
        float2 FO = make_float2(exp2i(E - Em),  exp2i(E - Em));
        float2 FN = make_float2(exp2i(En - Em), exp2i(En - Em));
        float2 V[8];
        #pragma unroll
        for (int j = 0; j < 4; ++j) V[j]     = mul2(N[j], FN);
        #pragma unroll
        for (int j = 0; j < 4; ++j) V[4 + j] = mul2(A[j], FO);

        // 4-layer packed pyramid (pairs 4i-3..4i+3 down to 4i..4i+3).
        float2 L1[7], L2[6], L3[5];
        #pragma unroll
        for (int k = 0; k < 7; ++k) L1[k] = upd(V[k+1],  V[k],  sk[k],   P1[k]);
        #pragma unroll
        for (int k = 0; k < 6; ++k) L2[k] = upd(L1[k+1], L1[k], sk[k+1], P2[k]);
        #pragma unroll
        for (int k = 0; k < 5; ++k) L3[k] = upd(L2[k+1], L2[k], sk[k+2], P3[k]);
        #pragma unroll
        for (int k = 0; k < 4; ++k) A[k]  = upd(L3[k+1], L3[k], sk[k+3], P4[k]);

        // Renormalize: divide by exact 2^e where e = exponent of the max.
        float m = fmaxf(fmaxf(fmaxf(A[0].x,A[0].y), fmaxf(A[1].x,A[1].y)),
                        fmaxf(fmaxf(A[2].x,A[2].y), fmaxf(A[3].x,A[3].y)));
        int e = ((__float_as_int(m) >> 23) & 255) - 127;
        float2 S = make_float2(exp2i(-e), exp2i(-e));
        #pragma unroll
        for (int j = 0; j < 4; ++j) A[j] = mul2(A[j], S);
        E = Em + e;
    }

    // Tail: 0..3 single steps.
    for (; t < Tb; ++t) {
        float2 N3; int En;
        N3.x = __shfl_up_sync(0xffffffffu, A[3].x, 1);
        N3.y = __shfl_up_sync(0xffffffffu, A[3].y, 1);
        En   = __shfl_up_sync(0xffffffffu, E, 1);
        if (i == 0) { N3 = make_float2(0.f, 0.f); En = E; }
        int Em = E > En ? E : En;
        float fo = exp2i(E - Em), fn = exp2i(En - Em);
        N3 = mul2(N3, make_float2(fn, fn));
        float2 FO = make_float2(fo, fo);
        #pragma unroll
        for (int j = 0; j < 4; ++j) A[j] = mul2(A[j], FO);

        const char* rp = base + (size_t)t * 512;
        float blv = *(const float*)(rp + 508) + EPSV;
        float2 O[4]; float2 prev = N3;
        #pragma unroll
        for (int k = 0; k < 4; ++k) {
            float pv = *(const float*)(rp + lofs[k + 3]) + EPSV;
            O[k] = upd(A[k], prev, sk[k + 3], make_float2(blv, pv));
            prev = A[k];
        }
        #pragma unroll
        for (int k = 0; k < 4; ++k) A[k] = O[k];

        float m = fmaxf(fmaxf(fmaxf(A[0].x,A[0].y), fmaxf(A[1].x,A[1].y)),
                        fmaxf(fmaxf(A[2].x,A[2].y), fmaxf(A[3].x,A[3].y)));
        int e = ((__float_as_int(m) >> 23) & 255) - 127;
        float2 S = make_float2(exp2i(-e), exp2i(-e));
        #pragma unroll
        for (int j = 0; j < 4; ++j) A[j] = mul2(A[j], S);
        E = Em + e;
    }

    // Readout: positions smax (thread smax>>3) and smax-1.
    __shared__ float fm[NT * 8];
    __shared__ int   fe[NT];
    #pragma unroll
    for (int j = 0; j < 4; ++j) {
        fm[i * 8 + 2 * j]     = A[j].x;
        fm[i * 8 + 2 * j + 1] = A[j].y;
    }
    fe[i] = E;
    __syncwarp();
    if (i == 0) {
        float mL = fm[smax];     int EL = fe[smax >> 3];
        float mP = fm[smax - 1]; int EP = fe[(smax - 1) >> 3];
        int Em = EL > EP ? EL : EP;
        float r = mL * exp2i(EL - Em) + mP * exp2i(EP - Em);
        out[b] = -LN2F * (lg2a(r) + (float)Em);
    }
}

extern "C" void kernel_launch(void* const* d_in, const int* in_sizes, int n_in,
                              void* d_out, int out_size)
{
    const int*   y_true    = (const int*)  d_in[0];  // [B,L] int32
    const float* y_pred    = (const float*)d_in[1];  // [B,T,C] float32
    const int*   input_len = (const int*)  d_in[2];  // [B] int32
    const int*   label_len = (const int*)  d_in[3];  // [B] int32
    float*       out       = (float*)d_out;          // [B,1] float32

    ctc_loss_kernel<<<Bc, NT>>>(y_true, y_pred, input_len, label_len, out);
}

// round 11
// speedup vs baseline: 1.6282x; 1.6282x over previous
#include <cuda_runtime.h>
#include <math.h>

// CTC loss forward. 4 warps/CTA (1 per SMSP), two positions per thread in
// f32x2, block-floating-point alpha: linear float2 mantissa + per-thread
// int exponent. ZERO MUFU in the main loop (the log<->linear roundtrip of
// R9 is replaced by exact power-of-two exponent alignment, pure ALU/FMA).
// B=64, T=1000, C=128 (blank=127), L=100, S=201.
// Thread i owns extended positions (2i, 2i+1): 2i is blank, 2i+1 labels[i].
// Per iteration (4 time steps, one __syncthreads):
//   publish {mant,E}; window = 5 pairs; Em = max exponent; align each pair
//   by exact 2^(Ej-Em); 4-layer packed pyramid (4+3+2+1 f32x2 updates);
//   renormalize by exact 2^-e, E = Em + e.

#define Bc 64
#define Tc 1000
#define Cc 128
#define Lc 100
#define NTHREADS 128
#define NPAIR 128
#define PADP 4
#define EDEAD (-(1 << 29))

#define EPSV (1e-7f)
#define LN2F 0.6931471805599453f

__device__ __forceinline__ float lg2a(float x) {
    float y; asm("lg2.approx.f32 %0, %1;" : "=f"(y) : "f"(x)); return y;
}
__device__ __forceinline__ float2 add2(float2 a, float2 b) {
    float2 r;
    asm("{\n\t.reg .b64 A,B,D;\n\t"
        "mov.b64 A,{%2,%3};\n\tmov.b64 B,{%4,%5};\n\t"
        "add.rn.f32x2 D,A,B;\n\t"
        "mov.b64 {%0,%1},D;\n\t}"
        : "=f"(r.x), "=f"(r.y)
        : "f"(a.x), "f"(a.y), "f"(b.x), "f"(b.y));
    return r;
}
__device__ __forceinline__ float2 mul2(float2 a, float2 b) {
    float2 r;
    asm("{\n\t.reg .b64 A,B,D;\n\t"
        "mov.b64 A,{%2,%3};\n\tmov.b64 B,{%4,%5};\n\t"
        "mul.rn.f32x2 D,A,B;\n\t"
        "mov.b64 {%0,%1},D;\n\t}"
        : "=f"(r.x), "=f"(r.y)
        : "f"(a.x), "f"(a.y), "f"(b.x), "f"(b.y));
    return r;
}
__device__ __forceinline__ float2 fma2(float2 a, float2 b, float2 c) {
    float2 r;
    asm("{\n\t.reg .b64 A,B,C,D;\n\t"
        "mov.b64 A,{%2,%3};\n\tmov.b64 B,{%4,%5};\n\tmov.b64 C,{%6,%7};\n\t"
        "fma.rn.f32x2 D,A,B,C;\n\t"
        "mov.b64 {%0,%1},D;\n\t}"
        : "=f"(r.x), "=f"(r.y)
        : "f"(a.x), "f"(a.y), "f"(b.x), "f"(b.y), "f"(c.x), "f"(c.y));
    return r;
}
// Exact 2^d (d int), clamped to 0 below representable range.
__device__ __forceinline__ float exp2i(int d) {
    int e = 127 + d; e = e < 0 ? 0 : e;
    return __int_as_float(e << 23);
}
// One CTC step for pair j: lo = (v2j + v2j-1)*pb; hi = (v2j+1 + v2j + sk*v2j-1)*po
__device__ __forceinline__ float2 upd(float2 Q, float2 Qm1, float2 SK, float2 P) {
    float2 S1 = make_float2(Qm1.y, Q.x);
    return mul2(fma2(SK, Qm1, add2(Q, S1)), P);
}

__global__ __launch_bounds__(NTHREADS, 1)
void ctc_loss_kernel(const int* __restrict__ y_true,
                     const float* __restrict__ y_pred,
                     const int* __restrict__ input_len,
                     const int* __restrict__ label_len,
                     float* __restrict__ out)
{
    const int b = blockIdx.x;
    const int i = threadIdx.x;                 // pair index

    __shared__ float2 mbuf[2][PADP + NPAIR];
    __shared__ int    ebuf[2][PADP + NPAIR];
    __shared__ int    labels[Lc];

    if (i < Lc) labels[i] = y_true[b * Lc + i];
    if (i < PADP) {
        mbuf[0][i] = make_float2(0.f, 0.f);
        mbuf[1][i] = make_float2(0.f, 0.f);
        ebuf[0][i] = EDEAD;
        ebuf[1][i] = EDEAD;
    }
    __syncthreads();

    // Static per-thread info for pairs i-3..i (odd-position class + skip).
    int    oc[4];
    float2 SK[4];
    #pragma unroll
    for (int k = 0; k < 4; ++k) {
        int pj = i - 3 + k;
        int cj = pj < 0 ? 0 : (pj > Lc - 1 ? Lc - 1 : pj);
        oc[k] = labels[cj];
        int cjm = cj > 0 ? cj - 1 : 0;
        float sk = (pj >= 1 && labels[cj] != labels[cjm]) ? 1.f : 0.f;
        SK[k] = make_float2(0.f, sk);
    }

    int Tb = input_len[b]; if (Tb > Tc) Tb = Tc;
    const int smax = 2 * label_len[b];
    const float* base = y_pred + (size_t)b * Tc * Cc;

    // BFP init: pair 0 alive with E=0, others dead.
    float2 A = make_float2(0.f, 0.f);
    int    E = EDEAD;
    if (i == 0) {
        A = make_float2(base[Cc - 1] + EPSV, base[oc[3]] + EPSV);
        E = 0;
    }

    // Prefetch probability scalars for the first iteration (rows 1..4).
    float bl[4], o0v, o1v[2], o2v[3], o3v[4];
    {
        const float* R = base + Cc;    // row 1 (Tb >= 500: rows 1..4 valid)
        bl[0] = R[Cc - 1]; bl[1] = R[Cc + Cc - 1];
        bl[2] = R[2 * Cc + Cc - 1]; bl[3] = R[3 * Cc + Cc - 1];
        o0v   = R[oc[0]];
        o1v[0] = R[oc[1]]; o1v[1] = R[Cc + oc[1]];
        o2v[0] = R[oc[2]]; o2v[1] = R[Cc + oc[2]]; o2v[2] = R[2 * Cc + oc[2]];
        o3v[0] = R[oc[3]]; o3v[1] = R[Cc + oc[3]];
        o3v[2] = R[2 * Cc + oc[3]]; o3v[3] = R[3 * Cc + oc[3]];
    }

    int it = 0;
    int t = 1;

    for (; t + 3 < Tb; t += 4, ++it) {
        // Pack current probabilities (+eps).
        float b0 = bl[0] + EPSV, b1 = bl[1] + EPSV;
        float b2 = bl[2] + EPSV, b3 = bl[3] + EPSV;
        float2 P1[4] = { make_float2(b0, o0v   + EPSV),
                         make_float2(b0, o1v[0] + EPSV),
                         make_float2(b0, o2v[0] + EPSV),
                         make_float2(b0, o3v[0] + EPSV) };
        float2 P2[3] = { make_float2(b1, o1v[1] + EPSV),
                         make_float2(b1, o2v[1] + EPSV),
                         make_float2(b1, o3v[1] + EPSV) };
        float2 P3[2] = { make_float2(b2, o2v[2] + EPSV),
                         make_float2(b2, o3v[2] + EPSV) };
        float2 P4    =   make_float2(b3, o3v[3] + EPSV);

        float2* mb = mbuf[it & 1];
        int*    eb = ebuf[it & 1];
        mb[PADP + i] = A;
        eb[PADP + i] = E;
        __syncthreads();

        // Prefetch next iteration's scalars (row base clamped in-bounds).
        {
            int r0 = t + 4; if (r0 > Tb - 4) r0 = Tb - 4;
            const float* R = base + (size_t)r0 * Cc;
            bl[0] = R[Cc - 1]; bl[1] = R[Cc + Cc - 1];
            bl[2] = R[2 * Cc + Cc - 1]; bl[3] = R[3 * Cc + Cc - 1];
            o0v   = R[oc[0]];
            o1v[0] = R[oc[1]]; o1v[1] = R[Cc + oc[1]];
            o2v[0] = R[oc[2]]; o2v[1] = R[Cc + oc[2]]; o2v[2] = R[2 * Cc + oc[2]];
            o3v[0] = R[oc[3]]; o3v[1] = R[Cc + oc[3]];
            o3v[2] = R[2 * Cc + oc[3]]; o3v[3] = R[3 * Cc + oc[3]];
        }

        // Window: pairs i-4..i-1 from shared (+ exponents), own in registers.
        float2 W[4]; int Ew[4];
        #pragma unroll
        for (int j = 0; j < 4; ++j) { W[j] = mb[i + j]; Ew[j] = eb[i + j]; }

        // Align to max exponent (exact powers of two).
        int Em = E;
        #pragma unroll
        for (int j = 0; j < 4; ++j) Em = Ew[j] > Em ? Ew[j] : Em;

        float2 V[5];
        #pragma unroll
        for (int j = 0; j < 4; ++j) {
            float f = exp2i(Ew[j] - Em);
            V[j] = mul2(W[j], make_float2(f, f));
        }
        {
            float f = exp2i(E - Em);
            V[4] = mul2(A, make_float2(f, f));
        }

        // 4-layer packed pyramid.
        float2 L1[4];
        #pragma unroll
        for (int k = 0; k < 4; ++k) L1[k] = upd(V[k + 1], V[k], SK[k], P1[k]);
        float2 L2[3];
        #pragma unroll
        for (int k = 0; k < 3; ++k) L2[k] = upd(L1[k + 1], L1[k], SK[k + 1], P2[k]);
        float2 L3[2];
        #pragma unroll
        for (int k = 0; k < 2; ++k) L3[k] = upd(L2[k + 1], L2[k], SK[k + 2], P3[k]);
        A = upd(L3[1], L3[0], SK[3], P4);

        // Renormalize by exact 2^-e (e = exponent of the pair max).
        float m = fmaxf(A.x, A.y);
        int e = ((__float_as_int(m) >> 23) & 255) - 127;
        float sfac = exp2i(-e);
        A = mul2(A, make_float2(sfac, sfac));
        E = Em + e;
    }

    // Tail: 0..3 single steps (same BFP protocol, 1-pair window).
    for (; t < Tb; ++t, ++it) {
        float2* mb = mbuf[it & 1];
        int*    eb = ebuf[it & 1];
        mb[PADP + i] = A;
        eb[PADP + i] = E;
        __syncthreads();
        float2 N = mb[PADP + i - 1];
        int   En = eb[PADP + i - 1];
        int   Em = E > En ? E : En;
        float fo = exp2i(E - Em), fn = exp2i(En - Em);
        float2 Vo = mul2(A, make_float2(fo, fo));
        float2 Vn = mul2(N, make_float2(fn, fn));
        float pb = base[(size_t)t * Cc + (Cc - 1)] + EPSV;
        float po = base[(size_t)t * Cc + oc[3]]    + EPSV;
        A = upd(Vo, Vn, SK[3], make_float2(pb, po));
        float m = fmaxf(A.x, A.y);
        int e = ((__float_as_int(m) >> 23) & 255) - 127;
        float sfac = exp2i(-e);
        A = mul2(A, make_float2(sfac, sfac));
        E = Em + e;
    }

    // Final readout: positions smax (pair smax/2, lo) and smax-1
    // (pair smax/2-1, hi). smax is even and >= 100.
    float2* mb = mbuf[it & 1];
    int*    eb = ebuf[it & 1];
    mb[PADP + i] = A;
    eb[PADP + i] = E;
    __syncthreads();
    if (i == 0) {
        int   jL = smax >> 1;
        float mL = mb[PADP + jL].x;     int EL = eb[PADP + jL];
        float mP = mb[PADP + jL - 1].y; int EP = eb[PADP + jL - 1];
        int Em = EL > EP ? EL : EP;
        float r = mL * exp2i(EL - Em) + mP * exp2i(EP - Em);
        out[b] = -LN2F * (lg2a(r) + (float)Em);
    }
}

extern "C" void kernel_launch(void* const* d_in, const int* in_sizes, int n_in,
                              void* d_out, int out_size)
{
    const int*   y_true    = (const int*)  d_in[0];  // [B,L] int32
    const float* y_pred    = (const float*)d_in[1];  // [B,T,C] float32
    const int*   input_len = (const int*)  d_in[2];  // [B] int32
    const int*   label_len = (const int*)  d_in[3];  // [B] int32
    float*       out       = (float*)d_out;          // [B,1] float32

    ctc_loss_kernel<<<Bc, NTHREADS>>>(y_true, y_pred, input_len, label_len, out);
}